// round 8
// baseline (speedup 1.0000x reference)
#include <cuda_runtime.h>
#include <cstdint>

// Problem constants (fixed by the reference):
#define TT 512          // time steps
#define NB 32           // batch
#define CC 8000         // classes
#define SS 40           // max target length
#define SE 81           // 2*SS + 1 expanded-with-blank length
#define DEPTH 16        // register-ring prefetch depth (rows in flight)
#define SPW 27          // slots per warp (3 warps x 27 = 81)

#define LOG2E 1.4426950408889634f
#define LN2   0.6931471805599453f
#define TINY2 (-126.0f)          // log2(float32 tiny) == log(tiny) * log2(e)
#define NEG2  (-1e30f)           // "minus infinity" sentinel for LSE

__device__ __forceinline__ float ex2f(float x) {
    float r; asm("ex2.approx.ftz.f32 %0, %1;" : "=f"(r) : "f"(x)); return r;
}
__device__ __forceinline__ float lg2f(float x) {
    float r; asm("lg2.approx.f32 %0, %1;" : "=f"(r) : "f"(x)); return r;
}
// Volatile LDG: cannot be deleted or sunk to the consumer by the compiler.
#define LDGV(dst, addr) \
    asm volatile("ld.global.nc.f32 %0, [%1];" : "=f"(dst) : "l"(addr))

// Three warps per batch item, one slot per lane, time-skewed wavefront:
// at iteration i, warp w computes time step tau = i - w. Warp w+1's lanes
// 0,1 need warp w's slots (top two) from tau-1, which warp w produced TWO
// iterations earlier -> a __syncthreads every 2 iterations is sufficient,
// with a depth-4 smem boundary ring:
//   write at iter i -> slot  i    & 3   (compile-time under unroll)
//   read  at iter i -> slot (i+2) & 3   (producer's write from iter i-2)
// Max skew between bars is 1 iter, so concurrently-touched write slots
// {i,i+1}&3 and read slots {i+2,i+3}&3 are disjoint. Warm-up/drain steps
// are discarded by a predicated commit, so every warp runs identical
// branch-free code.
__global__ void __launch_bounds__(96, 1)
ctc_kernel(const float* __restrict__ lp,
           const int*   __restrict__ tg,
           const int*   __restrict__ tlen,
           float*       __restrict__ out)
{
    __shared__ float bnd[4][4][2];   // [ring slot][owner warp+1][which]
    __shared__ float sa[84];

    const int n    = blockIdx.x;
    const int w    = threadIdx.x >> 5;
    const int lane = threadIdx.x & 31;
    const int s    = w * SPW + lane;           // valid when lane < 27
    const bool owner = (lane < SPW);

    // Loop-invariant class column and skip flag for this slot.
    // et[s] = blank(0) for even s, targets[n, s>>1] for odd s.
    int  c = 0; bool k = false;
    if (owner && (s & 1)) {
        c = tg[n * SS + (s >> 1)];
        if (s >= 3) k = (c != tg[n * SS + (s >> 1) - 1]);
    }

    const size_t strideE = (size_t)NB * CC;         // elements per time row
    const float* base = lp + (size_t)n * CC + c;    // this lane's column

    // Register-ring prologue: slot d holds row max(d+1-w, 0) (warm-up rows
    // clamp to 0; their results are discarded by the predicated commit).
    float rg[DEPTH];
    #pragma unroll
    for (int d = 0; d < DEPTH; ++d) {
        int row = d + 1 - w; if (row < 0) row = 0;
        LDGV(rg[d], base + (size_t)row * strideE);
    }

    // alpha at tau=0 (base-2): slot0 = lp(0,blank), slot1 = lp(0,target0).
    float a = TINY2;
    {
        float v0 = __ldg(base);                 // row 0 of this lane's column
        if (w == 0 && lane < 2) a = v0 * LOG2E;
    }

    // Boundary ring init: warp -1 (consumer warp 0) sees NEG2 ("no slot");
    // producers publish their tau=0 values (TINY2 on lanes 25/26) everywhere.
    if (threadIdx.x < 8) bnd[threadIdx.x >> 1][0][threadIdx.x & 1] = NEG2;
    if (lane == 25) { bnd[0][w+1][0]=a; bnd[1][w+1][0]=a; bnd[2][w+1][0]=a; bnd[3][w+1][0]=a; }
    if (lane == 26) { bnd[0][w+1][1]=a; bnd[1][w+1][1]=a; bnd[2][w+1][1]=a; bnd[3][w+1][1]=a; }
    __syncthreads();

    // One wavefront iteration i = tb + d (tb ≡ 1 mod 16, so i&3 == (d+1)&3).
    #define STEP(d, tb)                                                     \
    {                                                                       \
        float lpv = rg[d];                                                  \
        int row = (tb) + (d) + DEPTH - w;                                   \
        row = min(row, TT - 1);                                             \
        LDGV(rg[d], base + (size_t)row * strideE);                          \
        float pm1 = __shfl_up_sync(0xffffffffu, a, 1);                      \
        float pm2 = __shfl_up_sync(0xffffffffu, a, 2);                      \
        float b0 = bnd[((d) + 3) & 3][w][0];   /* prev warp slot s0-2 */    \
        float b1 = bnd[((d) + 3) & 3][w][1];   /* prev warp slot s0-1 */    \
        float bx = (lane == 0) ? b0 : b1;                                   \
        pm1 = (lane == 0) ? b1 : pm1;                                       \
        pm2 = (lane <  2) ? bx : pm2;                                       \
        float z  = k ? pm2 : NEG2;                                          \
        float hi = fmaxf(a, pm1), lo = fminf(a, pm1);                       \
        float m  = fmaxf(hi, z),  mid = fminf(hi, z);                       \
        float e  = ex2f(lo - m) + ex2f(mid - m);                            \
        float na = fmaf(lpv, LOG2E, m + lg2f(1.0f + e));                    \
        unsigned act = (unsigned)((tb) + (d) - w - 1);  /* tau-1 */         \
        a = (act <= (unsigned)(TT - 2)) ? na : a;                           \
        if (lane == 25) bnd[((d) + 1) & 3][w + 1][0] = a;                   \
        if (lane == 26) bnd[((d) + 1) & 3][w + 1][1] = a;                   \
        if ((d) & 1) __syncthreads();                                       \
    }

    // Iterations i = 1..512 (32 blocks of 16), then one peel (i = 513) so
    // the last warp (w=2) commits tau = 511.
    for (int tb = 1; tb <= 497; tb += 16) {
        STEP(0,  tb) STEP(1,  tb) STEP(2,  tb) STEP(3,  tb)
        STEP(4,  tb) STEP(5,  tb) STEP(6,  tb) STEP(7,  tb)
        STEP(8,  tb) STEP(9,  tb) STEP(10, tb) STEP(11, tb)
        STEP(12, tb) STEP(13, tb) STEP(14, tb) STEP(15, tb)
    }
    STEP(0, 513)
    #undef STEP

    __syncthreads();
    if (owner) sa[s] = a;
    __syncthreads();

    // Final combine: loss = logadd(alpha[l-1], alpha[l-2]), l = 2*tl + 1,
    // converted back to natural log.
    if (threadIdx.x == 0) {
        int tl = tlen[n];
        int l  = 2 * tl + 1;
        float x = sa[l - 1];
        float y = sa[l - 2];
        float m = fmaxf(x, y);
        float s2 = m + lg2f(1.0f + ex2f(fminf(x, y) - m));
        out[n] = -(s2 * LN2) / (float)tl;
    }
}

// ---------------------------------------------------------------------------
// Inputs: [0]=log_probs f32 (T,N,C), [1]=targets i32 (N,S),
//         [2]=input_lengths i32 (ignored, as in reference), [3]=target_lengths i32.
// Single kernel, graph-capturable, allocation-free.
// ---------------------------------------------------------------------------
extern "C" void kernel_launch(void* const* d_in, const int* in_sizes, int n_in,
                              void* d_out, int out_size) {
    const float* log_probs = (const float*)d_in[0];
    const int*   targets   = (const int*)d_in[1];
    const int*   tgt_lens  = (const int*)d_in[3];
    float*       out       = (float*)d_out;

    ctc_kernel<<<NB, 96>>>(log_probs, targets, tgt_lens, out);
}